// round 6
// baseline (speedup 1.0000x reference)
#include <cuda_runtime.h>
#include <cuda_bf16.h>
#include <math.h>
#include <stdint.h>

#define T_TOK 2048
#define HDIM  1024
#define FDIM  512
#define NE    32
#define TOPK  4
#define SLOTS (T_TOK * TOPK)

// ---------------- scratch ----------------
__device__ int   g_cnt[NE];
__device__ int   g_base[NE];
__device__ int   g_btok[NE * T_TOK];
__device__ float g_bw  [NE * T_TOK];
__device__ int   g_pe  [T_TOK * TOPK];
__device__ int   g_pp  [T_TOK * TOPK];
__device__ __nv_bfloat16 g_hhi[(size_t)SLOTS * FDIM];   // 8 MB
__device__ __nv_bfloat16 g_hlo[(size_t)SLOTS * FDIM];   // 8 MB
__device__ float g_ybuf[(size_t)SLOTS * HDIM];          // 32 MB

// precomputed split-bf16 operands
__device__ __nv_bfloat16 g_xh [(size_t)T_TOK * HDIM];            // 4 MB
__device__ __nv_bfloat16 g_xl [(size_t)T_TOK * HDIM];
__device__ __nv_bfloat16 g_wgh[(size_t)NE * FDIM * HDIM];        // 32 MB each
__device__ __nv_bfloat16 g_wgl[(size_t)NE * FDIM * HDIM];
__device__ __nv_bfloat16 g_wuh[(size_t)NE * FDIM * HDIM];
__device__ __nv_bfloat16 g_wul[(size_t)NE * FDIM * HDIM];
__device__ __nv_bfloat16 g_wdh[(size_t)NE * HDIM * FDIM];
__device__ __nv_bfloat16 g_wdl[(size_t)NE * HDIM * FDIM];

// ---------------- helpers ----------------
__device__ __forceinline__ void mma16816(float* d, const uint32_t* a, const uint32_t* b) {
    asm volatile(
        "mma.sync.aligned.m16n8k16.row.col.f32.bf16.bf16.f32 "
        "{%0,%1,%2,%3}, {%4,%5,%6,%7}, {%8,%9}, {%0,%1,%2,%3};\n"
        : "+f"(d[0]), "+f"(d[1]), "+f"(d[2]), "+f"(d[3])
        : "r"(a[0]), "r"(a[1]), "r"(a[2]), "r"(a[3]), "r"(b[0]), "r"(b[1]));
}

__device__ __forceinline__ void split2(float a, float b, uint32_t& h, uint32_t& l) {
    __nv_bfloat162 hh = __floats2bfloat162_rn(a, b);
    float2 hf = __bfloat1622float2(hh);
    __nv_bfloat162 ll = __floats2bfloat162_rn(a - hf.x, b - hf.y);
    h = *reinterpret_cast<uint32_t*>(&hh);
    l = *reinterpret_cast<uint32_t*>(&ll);
}

__device__ __forceinline__ void split8(const float* x, uint4& hv, uint4& lv) {
    uint32_t h[4], l[4];
#pragma unroll
    for (int i = 0; i < 4; i++) split2(x[2*i], x[2*i+1], h[i], l[i]);
    hv = make_uint4(h[0], h[1], h[2], h[3]);
    lv = make_uint4(l[0], l[1], l[2], l[3]);
}

__device__ __forceinline__ uint32_t smem_u32(const void* p) {
    uint32_t a;
    asm("{ .reg .u64 t; cvta.to.shared.u64 t, %1; cvt.u32.u64 %0, t; }" : "=r"(a) : "l"(p));
    return a;
}
__device__ __forceinline__ void cpa16(uint32_t dst, const void* src) {
    asm volatile("cp.async.cg.shared.global [%0], [%1], 16;" :: "r"(dst), "l"(src));
}
#define CP_COMMIT() asm volatile("cp.async.commit_group;" ::: "memory")
template<int N> __device__ __forceinline__ void cp_wait() {
    asm volatile("cp.async.wait_group %0;" :: "n"(N) : "memory");
}

// ---------------- conversion kernel ----------------
__global__ void convert_split(const float* __restrict__ src,
                              __nv_bfloat16* __restrict__ dh,
                              __nv_bfloat16* __restrict__ dl, int n8) {
    int i = blockIdx.x * blockDim.x + threadIdx.x;
    if (i >= n8) return;
    float x[8];
    *(float4*)&x[0] = *(const float4*)(src + 8*(size_t)i);
    *(float4*)&x[4] = *(const float4*)(src + 8*(size_t)i + 4);
    uint4 hv, lv; split8(x, hv, lv);
    *(uint4*)(dh + 8*(size_t)i) = hv;
    *(uint4*)(dl + 8*(size_t)i) = lv;
}

// ---------------- router GEMM ----------------
__global__ void router_gemm(const float* __restrict__ xr, const float* __restrict__ wr,
                            float* __restrict__ logits) {
    __shared__ float Xs[16][68];
    __shared__ float Ws[16][36];
    int tid = threadIdx.x;
    int t0  = blockIdx.x * 64;
    int tx = tid & 31, ty = tid >> 5;
    float acc[8];
#pragma unroll
    for (int j = 0; j < 8; j++) acc[j] = 0.f;
    int mL = tid >> 2, ksL = tid & 3;
    for (int k0 = 0; k0 < HDIM; k0 += 16) {
        float4 v = *(const float4*)(xr + (size_t)(t0 + mL) * HDIM + k0 + ksL * 4);
        Xs[ksL*4+0][mL] = v.x; Xs[ksL*4+1][mL] = v.y;
        Xs[ksL*4+2][mL] = v.z; Xs[ksL*4+3][mL] = v.w;
        if (tid < 128) {
            int n = tid >> 2, ks = tid & 3;
            float4 w = *(const float4*)(wr + (size_t)n * HDIM + k0 + ks * 4);
            Ws[ks*4+0][n] = w.x; Ws[ks*4+1][n] = w.y;
            Ws[ks*4+2][n] = w.z; Ws[ks*4+3][n] = w.w;
        }
        __syncthreads();
#pragma unroll
        for (int kk = 0; kk < 16; kk++) {
            float b = Ws[kk][tx];
            float4 a0 = *(const float4*)&Xs[kk][ty*8];
            float4 a1 = *(const float4*)&Xs[kk][ty*8+4];
            acc[0] += a0.x*b; acc[1] += a0.y*b; acc[2] += a0.z*b; acc[3] += a0.w*b;
            acc[4] += a1.x*b; acc[5] += a1.y*b; acc[6] += a1.z*b; acc[7] += a1.w*b;
        }
        __syncthreads();
    }
#pragma unroll
    for (int j = 0; j < 8; j++)
        logits[(size_t)(t0 + ty*8 + j) * NE + tx] = acc[j];
}

__global__ void zero_cnt() { if (threadIdx.x < NE) g_cnt[threadIdx.x] = 0; }

__global__ void topk_kernel(const float* __restrict__ logits) {
    int t = blockIdx.x * blockDim.x + threadIdx.x;
    if (t >= T_TOK) return;
    float v[NE];
#pragma unroll
    for (int e = 0; e < NE; e++) v[e] = logits[(size_t)t * NE + e];
    float val[TOPK]; int sel[TOPK];
#pragma unroll
    for (int kk = 0; kk < TOPK; kk++) {
        float best = -INFINITY; int bi = 0;
#pragma unroll
        for (int e = 0; e < NE; e++)
            if (v[e] > best) { best = v[e]; bi = e; }
        val[kk] = best; sel[kk] = bi; v[bi] = -INFINITY;
    }
    float mx = val[0];
    float w[TOPK], s = 0.f;
#pragma unroll
    for (int kk = 0; kk < TOPK; kk++) { w[kk] = expf(val[kk] - mx); s += w[kk]; }
    float inv = 1.f / s;
#pragma unroll
    for (int kk = 0; kk < TOPK; kk++) {
        int e = sel[kk];
        int pos = atomicAdd(&g_cnt[e], 1);
        g_btok[e * T_TOK + pos] = t;
        g_bw  [e * T_TOK + pos] = w[kk] * inv;
        g_pe[t * TOPK + kk] = e;
        g_pp[t * TOPK + kk] = pos;
    }
}

__global__ void prefix_kernel() {
    if (threadIdx.x == 0) {
        int s = 0;
        for (int e = 0; e < NE; e++) { g_base[e] = s; s += g_cnt[e]; }
    }
}

// ================= gate/up HMMA kernel (cp.async double-buffered) =================
// CTA: 128 tokens x 64 F-cols, 8 warps (wm=wid&3, wn=wid>>2), BK=32.
// SMEM row pitch 80B (40 bf16), conflict-free.
// Stage layout (bytes): XH 0, XL 10240, GH 20480, GL 25600, UH 30720, UL 35840; stage=40960
#define PADK 40
#define GU_STAGE 40960
#define GU_SMEM  (2 * GU_STAGE)
__global__ void __launch_bounds__(256) gateup_mma() {
    int e   = blockIdx.z;
    int cnt = g_cnt[e];
    int m0  = blockIdx.y * 128;
    if (m0 >= cnt) return;
    int f0 = blockIdx.x * 64;

    extern __shared__ __align__(128) char smem[];
    uint32_t sb = smem_u32(smem);

    int tid = threadIdx.x, wid = tid >> 5, lane = tid & 31;
    int wm = wid & 3, wn = wid >> 2;
    int g = lane >> 2, q = lane & 3;

    // loader roles
    int xrow = tid >> 1, xhalf = tid & 1;
    int tokL = g_btok[e * T_TOK + min(m0 + xrow, cnt - 1)];
    const __nv_bfloat16* xhs = g_xh + (size_t)tokL * HDIM + xhalf * 16;
    const __nv_bfloat16* xls = g_xl + (size_t)tokL * HDIM + xhalf * 16;
    int wrow = tid >> 2, wq = tid & 3;
    size_t woff = (size_t)e * FDIM * HDIM + (size_t)(f0 + wrow) * HDIM + wq * 8;
    uint32_t xdst = sb + (uint32_t)xrow * 80 + (uint32_t)xhalf * 32;
    uint32_t wdst = sb + 20480 + (uint32_t)wrow * 80 + (uint32_t)wq * 16;

    float accG[2][4][4] = {}, accU[2][4][4] = {};

    const int NC = HDIM / 32;
    // prefetch chunk 0 -> stage 0
    {
        cpa16(xdst, xhs); cpa16(xdst + 16, xhs + 8);
        cpa16(xdst + 10240, xls); cpa16(xdst + 10240 + 16, xls + 8);
        cpa16(wdst,         g_wgh + woff);
        cpa16(wdst +  5120, g_wgl + woff);
        cpa16(wdst + 10240, g_wuh + woff);
        cpa16(wdst + 15360, g_wul + woff);
        CP_COMMIT();
    }

    for (int ci = 0; ci < NC; ci++) {
        if (ci + 1 < NC) {
            uint32_t so = ((ci + 1) & 1) * GU_STAGE;
            int kk = (ci + 1) * 32;
            cpa16(xdst + so, xhs + kk); cpa16(xdst + so + 16, xhs + kk + 8);
            cpa16(xdst + so + 10240, xls + kk); cpa16(xdst + so + 10240 + 16, xls + kk + 8);
            cpa16(wdst + so,         g_wgh + woff + kk);
            cpa16(wdst + so +  5120, g_wgl + woff + kk);
            cpa16(wdst + so + 10240, g_wuh + woff + kk);
            cpa16(wdst + so + 15360, g_wul + woff + kk);
            CP_COMMIT();
            cp_wait<1>();
        } else {
            cp_wait<0>();
        }
        __syncthreads();

        const char* st = smem + (ci & 1) * GU_STAGE;
        const __nv_bfloat16* sXh = (const __nv_bfloat16*)(st);
        const __nv_bfloat16* sXl = (const __nv_bfloat16*)(st + 10240);
        const __nv_bfloat16* sGh = (const __nv_bfloat16*)(st + 20480);
        const __nv_bfloat16* sGl = (const __nv_bfloat16*)(st + 25600);
        const __nv_bfloat16* sUh = (const __nv_bfloat16*)(st + 30720);
        const __nv_bfloat16* sUl = (const __nv_bfloat16*)(st + 35840);

#pragma unroll
        for (int kt = 0; kt < 2; kt++) {
            int kc = kt * 16 + 2 * q;
            uint32_t axh[2][4], axl[2][4];
#pragma unroll
            for (int mt = 0; mt < 2; mt++) {
                int r = wm * 32 + mt * 16 + g;
                axh[mt][0] = *(const uint32_t*)&sXh[r*PADK + kc];
                axh[mt][1] = *(const uint32_t*)&sXh[(r+8)*PADK + kc];
                axh[mt][2] = *(const uint32_t*)&sXh[r*PADK + kc + 8];
                axh[mt][3] = *(const uint32_t*)&sXh[(r+8)*PADK + kc + 8];
                axl[mt][0] = *(const uint32_t*)&sXl[r*PADK + kc];
                axl[mt][1] = *(const uint32_t*)&sXl[(r+8)*PADK + kc];
                axl[mt][2] = *(const uint32_t*)&sXl[r*PADK + kc + 8];
                axl[mt][3] = *(const uint32_t*)&sXl[(r+8)*PADK + kc + 8];
            }
#pragma unroll
            for (int nt = 0; nt < 4; nt++) {
                int br = wn * 32 + nt * 8 + g;
                uint32_t bgh[2] = {*(const uint32_t*)&sGh[br*PADK + kc], *(const uint32_t*)&sGh[br*PADK + kc + 8]};
                uint32_t bgl[2] = {*(const uint32_t*)&sGl[br*PADK + kc], *(const uint32_t*)&sGl[br*PADK + kc + 8]};
                uint32_t buh[2] = {*(const uint32_t*)&sUh[br*PADK + kc], *(const uint32_t*)&sUh[br*PADK + kc + 8]};
                uint32_t bul[2] = {*(const uint32_t*)&sUl[br*PADK + kc], *(const uint32_t*)&sUl[br*PADK + kc + 8]};
#pragma unroll
                for (int mt = 0; mt < 2; mt++) {
                    mma16816(accG[mt][nt], axh[mt], bgh);
                    mma16816(accG[mt][nt], axl[mt], bgh);
                    mma16816(accG[mt][nt], axh[mt], bgl);
                    mma16816(accU[mt][nt], axh[mt], buh);
                    mma16816(accU[mt][nt], axl[mt], buh);
                    mma16816(accU[mt][nt], axh[mt], bul);
                }
            }
        }
        __syncthreads();
    }

    // epilogue: h = relu(G)*U, write bf16 hi/lo
    int base = g_base[e];
#pragma unroll
    for (int mt = 0; mt < 2; mt++) {
        int lm0 = wm * 32 + mt * 16 + g;
#pragma unroll
        for (int nt = 0; nt < 4; nt++) {
            int c = f0 + wn * 32 + nt * 8 + 2 * q;
            float* Gd = accG[mt][nt];
            float* Ud = accU[mt][nt];
            float v0 = fmaxf(Gd[0], 0.f) * Ud[0];
            float v1 = fmaxf(Gd[1], 0.f) * Ud[1];
            float v2 = fmaxf(Gd[2], 0.f) * Ud[2];
            float v3 = fmaxf(Gd[3], 0.f) * Ud[3];
            uint32_t h01, l01, h23, l23;
            split2(v0, v1, h01, l01);
            split2(v2, v3, h23, l23);
            int m = m0 + lm0;
            if (m < cnt) {
                size_t slot = (size_t)base + m;
                *(uint32_t*)(g_hhi + slot * FDIM + c) = h01;
                *(uint32_t*)(g_hlo + slot * FDIM + c) = l01;
            }
            if (m + 8 < cnt) {
                size_t slot = (size_t)base + m + 8;
                *(uint32_t*)(g_hhi + slot * FDIM + c) = h23;
                *(uint32_t*)(g_hlo + slot * FDIM + c) = l23;
            }
        }
    }
}

// ================= down HMMA kernel (cp.async double-buffered) =================
// Stage layout: XH 0, XL 10240, WH 20480, WL 25600; stage=30720
#define DN_STAGE 30720
#define DN_SMEM  (2 * DN_STAGE)
__global__ void __launch_bounds__(256) down_mma() {
    int e   = blockIdx.z;
    int cnt = g_cnt[e];
    int m0  = blockIdx.y * 128;
    if (m0 >= cnt) return;
    int h0 = blockIdx.x * 64;

    extern __shared__ __align__(128) char smem[];
    uint32_t sb = smem_u32(smem);

    int tid = threadIdx.x, wid = tid >> 5, lane = tid & 31;
    int wm = wid & 3, wn = wid >> 2;
    int g = lane >> 2, q = lane & 3;
    int base = g_base[e];

    int xrow = tid >> 1, xhalf = tid & 1;
    size_t slotR = (size_t)base + min(m0 + xrow, cnt - 1);
    const __nv_bfloat16* xhs = g_hhi + slotR * FDIM + xhalf * 16;
    const __nv_bfloat16* xls = g_hlo + slotR * FDIM + xhalf * 16;
    int wrow = tid >> 2, wq = tid & 3;
    size_t woff = (size_t)e * HDIM * FDIM + (size_t)(h0 + wrow) * FDIM + wq * 8;
    uint32_t xdst = sb + (uint32_t)xrow * 80 + (uint32_t)xhalf * 32;
    uint32_t wdst = sb + 20480 + (uint32_t)wrow * 80 + (uint32_t)wq * 16;

    float acc[2][4][4] = {};

    const int NC = FDIM / 32;
    {
        cpa16(xdst, xhs); cpa16(xdst + 16, xhs + 8);
        cpa16(xdst + 10240, xls); cpa16(xdst + 10240 + 16, xls + 8);
        cpa16(wdst,        g_wdh + woff);
        cpa16(wdst + 5120, g_wdl + woff);
        CP_COMMIT();
    }

    for (int ci = 0; ci < NC; ci++) {
        if (ci + 1 < NC) {
            uint32_t so = ((ci + 1) & 1) * DN_STAGE;
            int kk = (ci + 1) * 32;
            cpa16(xdst + so, xhs + kk); cpa16(xdst + so + 16, xhs + kk + 8);
            cpa16(xdst + so + 10240, xls + kk); cpa16(xdst + so + 10240 + 16, xls + kk + 8);
            cpa16(wdst + so,        g_wdh + woff + kk);
            cpa16(wdst + so + 5120, g_wdl + woff + kk);
            CP_COMMIT();
            cp_wait<1>();
        } else {
            cp_wait<0>();
        }
        __syncthreads();

        const char* st = smem + (ci & 1) * DN_STAGE;
        const __nv_bfloat16* sXh = (const __nv_bfloat16*)(st);
        const __nv_bfloat16* sXl = (const __nv_bfloat16*)(st + 10240);
        const __nv_bfloat16* sWh = (const __nv_bfloat16*)(st + 20480);
        const __nv_bfloat16* sWl = (const __nv_bfloat16*)(st + 25600);

#pragma unroll
        for (int kt = 0; kt < 2; kt++) {
            int kc = kt * 16 + 2 * q;
            uint32_t axh[2][4], axl[2][4];
#pragma unroll
            for (int mt = 0; mt < 2; mt++) {
                int r = wm * 32 + mt * 16 + g;
                axh[mt][0] = *(const uint32_t*)&sXh[r*PADK + kc];
                axh[mt][1] = *(const uint32_t*)&sXh[(r+8)*PADK + kc];
                axh[mt][2] = *(const uint32_t*)&sXh[r*PADK + kc + 8];
                axh[mt][3] = *(const uint32_t*)&sXh[(r+8)*PADK + kc + 8];
                axl[mt][0] = *(const uint32_t*)&sXl[r*PADK + kc];
                axl[mt][1] = *(const uint32_t*)&sXl[(r+8)*PADK + kc];
                axl[mt][2] = *(const uint32_t*)&sXl[r*PADK + kc + 8];
                axl[mt][3] = *(const uint32_t*)&sXl[(r+8)*PADK + kc + 8];
            }
#pragma unroll
            for (int nt = 0; nt < 4; nt++) {
                int br = wn * 32 + nt * 8 + g;
                uint32_t bwh[2] = {*(const uint32_t*)&sWh[br*PADK + kc], *(const uint32_t*)&sWh[br*PADK + kc + 8]};
                uint32_t bwl[2] = {*(const uint32_t*)&sWl[br*PADK + kc], *(const uint32_t*)&sWl[br*PADK + kc + 8]};
#pragma unroll
                for (int mt = 0; mt < 2; mt++) {
                    mma16816(acc[mt][nt], axh[mt], bwh);
                    mma16816(acc[mt][nt], axl[mt], bwh);
                    mma16816(acc[mt][nt], axh[mt], bwl);
                }
            }
        }
        __syncthreads();
    }

    // epilogue: y = acc * routing weight
#pragma unroll
    for (int mt = 0; mt < 2; mt++) {
        int lm0 = wm * 32 + mt * 16 + g;
        int m = m0 + lm0;
        float w0 = (m     < cnt) ? g_bw[e * T_TOK + m]     : 0.f;
        float w1 = (m + 8 < cnt) ? g_bw[e * T_TOK + m + 8] : 0.f;
#pragma unroll
        for (int nt = 0; nt < 4; nt++) {
            int c = h0 + wn * 32 + nt * 8 + 2 * q;
            float* D = acc[mt][nt];
            if (m < cnt) {
                float* py = g_ybuf + ((size_t)base + m) * HDIM + c;
                py[0] = D[0] * w0; py[1] = D[1] * w0;
            }
            if (m + 8 < cnt) {
                float* py = g_ybuf + ((size_t)base + m + 8) * HDIM + c;
                py[0] = D[2] * w1; py[1] = D[3] * w1;
            }
        }
    }
}

// ---------------- combine ----------------
__global__ void combine_kernel(float* __restrict__ out) {
    int t   = blockIdx.x;
    int tid = threadIdx.x;
    int sl[TOPK];
#pragma unroll
    for (int kk = 0; kk < TOPK; kk++)
        sl[kk] = g_base[g_pe[t*TOPK + kk]] + g_pp[t*TOPK + kk];
    int h = tid * 4;
    float4 a = *(const float4*)(g_ybuf + (size_t)sl[0] * HDIM + h);
    float4 b = *(const float4*)(g_ybuf + (size_t)sl[1] * HDIM + h);
    float4 c = *(const float4*)(g_ybuf + (size_t)sl[2] * HDIM + h);
    float4 d = *(const float4*)(g_ybuf + (size_t)sl[3] * HDIM + h);
    float4 r;
    r.x = a.x + b.x + c.x + d.x;
    r.y = a.y + b.y + c.y + d.y;
    r.z = a.z + b.z + c.z + d.z;
    r.w = a.w + b.w + c.w + d.w;
    *(float4*)(out + (size_t)t * HDIM + h) = r;
}

// ---------------- launch ----------------
extern "C" void kernel_launch(void* const* d_in, const int* in_sizes, int n_in,
                              void* d_out, int out_size) {
    const float* router_input = (const float*)d_in[0];
    const float* hidden       = (const float*)d_in[1];
    const float* w_router     = (const float*)d_in[2];
    const float* w_gate       = (const float*)d_in[3];
    const float* w_up         = (const float*)d_in[4];
    const float* w_down       = (const float*)d_in[5];
    float* out    = (float*)d_out;
    float* logits = out + (size_t)T_TOK * HDIM;

    static int attr_done = 0;
    if (!attr_done) {
        cudaFuncSetAttribute(gateup_mma, cudaFuncAttributeMaxDynamicSharedMemorySize, GU_SMEM);
        cudaFuncSetAttribute(down_mma,   cudaFuncAttributeMaxDynamicSharedMemorySize, DN_SMEM);
        attr_done = 1;
    }

    __nv_bfloat16 *xh, *xl, *wgh, *wgl, *wuh, *wul, *wdh, *wdl;
    cudaGetSymbolAddress((void**)&xh,  g_xh);  cudaGetSymbolAddress((void**)&xl,  g_xl);
    cudaGetSymbolAddress((void**)&wgh, g_wgh); cudaGetSymbolAddress((void**)&wgl, g_wgl);
    cudaGetSymbolAddress((void**)&wuh, g_wuh); cudaGetSymbolAddress((void**)&wul, g_wul);
    cudaGetSymbolAddress((void**)&wdh, g_wdh); cudaGetSymbolAddress((void**)&wdl, g_wdl);

    const int WN8 = NE * FDIM * HDIM / 8;   // 2,097,152
    const int XN8 = T_TOK * HDIM / 8;       // 262,144
    convert_split<<<WN8 / 256, 256>>>(w_gate, wgh, wgl, WN8);
    convert_split<<<WN8 / 256, 256>>>(w_up,   wuh, wul, WN8);
    convert_split<<<WN8 / 256, 256>>>(w_down, wdh, wdl, WN8);
    convert_split<<<XN8 / 256, 256>>>(hidden, xh,  xl,  XN8);

    zero_cnt<<<1, 32>>>();
    router_gemm<<<T_TOK / 64, 256>>>(router_input, w_router, logits);
    topk_kernel<<<T_TOK / 256, 256>>>(logits);
    prefix_kernel<<<1, 32>>>();
    gateup_mma<<<dim3(FDIM / 64, T_TOK / 128, NE), 256, GU_SMEM>>>();
    down_mma<<<dim3(HDIM / 64, T_TOK / 128, NE), 256, DN_SMEM>>>();
    combine_kernel<<<T_TOK, 256>>>(out);
}